// round 13
// baseline (speedup 1.0000x reference)
#include <cuda_runtime.h>

// Problem constants
#define BC        20      // B*C
#define HLEN      200     // his_length
#define DK        20
#define NROWS     4000    // BC*HLEN
#define ROW_ELEMS 8000    // D_INNER(400) * DK(20)
#define CTX_ELEMS (NROWS*DK)        // 80000
#define ATTN_OFF  CTX_ELEMS

// Projected q,k,v,c in TRANSPOSED layout: [bc][d][h] -> (bc*20+d)*200+h
__device__ float g_qT[CTX_ELEMS];
__device__ float g_kT[CTX_ELEMS];
__device__ float g_vT[CTX_ELEMS];
__device__ float g_cT[CTX_ELEMS];

// Producer-consumer sync (zero-initialized; restored to zero every launch:
// proj blocks raise g_cnt[bc] to 600, the 20th attn block of each bc resets).
__device__ int g_cnt[BC];
__device__ int g_done[BC];

#define PROJ_PER_BC   600               // 200 rows x 3 tensors
#define ATTN_PER_BC   20                // 20 tiles x 10 rows
#define BLOCKS_PER_BC (PROJ_PER_BC + ATTN_PER_BC)
#define TOTAL_BLOCKS  (BC * BLOCKS_PER_BC)   // 12400

// Shared memory (floats), union of both paths:
//  proj:    Ws @0 (400), red(float4) @400 (800 floats)
//  attn p1: ys @0 (40x200=8000), xs @8000 (400)
//  attn p2: vt @0 (20x200=4000), partials @4000 (256),
//           ctxp @4256 (250x21=5250), rss @9506 (10)
#define SMEM_FLOATS 9536
#define SMEM_BYTES  (SMEM_FLOATS * 4)

__global__ __launch_bounds__(256, 4) void mega_kernel(
    const float* __restrict__ Q, const float* __restrict__ K,
    const float* __restrict__ V, const float* __restrict__ cdd,
    const float* __restrict__ W, const float* __restrict__ bp,
    const float* __restrict__ W1, const float* __restrict__ b1p,
    float* __restrict__ out)
{
    extern __shared__ float sm[];
    const int bid = blockIdx.x;
    const int bc  = bid / BLOCKS_PER_BC;
    const int w   = bid - bc * BLOCKS_PER_BC;
    const int t   = threadIdx.x;

    if (w < PROJ_PER_BC) {
        // ================= PROJ block (producer) =================
        const int a = w / HLEN;          // tensor 0..2
        const int h = w - a * HLEN;      // row within bc
        const int r = bc * HLEN + h;

        float*  Ws  = sm;                        // 400
        float4* red = (float4*)(sm + 400);       // 200 float4

        for (int i = t; i < 400; i += 256) Ws[i] = W[i];
        __syncthreads();

        const float bias = __ldg(bp);
        const size_t base = (size_t)r * ROW_ELEMS;
        const float* src = (a == 0) ? (Q + base) : (a == 1) ? (K + base) : (V + base);
        float*       dst = (a == 0) ? g_qT : (a == 1) ? g_kT : g_vT;

        if (t < 200) {
            const float4* p = (const float4*)src;
            float a0 = 0.f, a1 = 0.f, a2 = 0.f, a3 = 0.f;
            #pragma unroll
            for (int j = 0; j < 10; j++) {
                const int i4 = t + 200 * j;
                const float4 v4 = p[i4];
                const float wv = Ws[(i4 * 4) / 20];   // same n for all 4 lanes
                a0 += v4.x * wv;
                a1 += v4.y * wv;
                a2 += v4.z * wv;
                a3 += v4.w * wv;
            }
            red[t] = make_float4(a0, a1, a2, a3);
        }
        __syncthreads();

        if (t < 20) {
            const int e  = t & 3;
            const int st = t >> 2;
            float s = bias;
            #pragma unroll 8
            for (int tp = st; tp < 200; tp += 5)
                s += ((const float*)&red[tp])[e];
            dst[(bc * DK + t) * HLEN + h] = s;
        }
        if (a == 2 && t < 20) {
            const float b1 = __ldg(b1p);
            const float* cb = cdd + (size_t)r * 400;
            float s = b1;
            #pragma unroll
            for (int n = 0; n < 20; n++)
                s += cb[n * 20 + t] * __ldg(W1 + n);
            g_cT[(bc * DK + t) * HLEN + h] = s;
        }

        // Release: make this block's writes visible, then signal.
        __threadfence();
        __syncthreads();
        if (t == 0) atomicAdd(&g_cnt[bc], 1);

    } else {
        // ================= ATTN block (consumer) =================
        const int mt = w - PROJ_PER_BC;   // 0..19
        const int m0 = mt * 10;

        float* ys       = sm;             // phase 1: [d][n] d<40
        float* xs       = sm + 8000;      // phase 1: [d][m] d<40, m<10
        float* vt       = sm;             // phase 2: [d][n] d<20 (overlays ys)
        float* partials = sm + 4000;      // 256
        float* ctxp     = sm + 4256;      // [t][d] t<250, stride 21
        float* rss      = sm + 9506;      // 10

        // Acquire: wait for all 600 proj blocks of this bc.
        if (t == 0) {
            while (*(volatile int*)&g_cnt[bc] < PROJ_PER_BC) {}
            __threadfence();
        }
        __syncthreads();

        // ---- phase 1 stage: ys = [k|c]^T, xs = [q|k] rows ----
        for (int i = t; i < 8000; i += 256) {
            const int d = i / 200, n = i - 200 * d;
            ys[i] = (d < 20) ? g_kT[(bc * DK + d) * HLEN + n]
                             : g_cT[(bc * DK + d - 20) * HLEN + n];
        }
        for (int i = t; i < 400; i += 256) {
            const int d = i / 10, m = i - 10 * d;
            xs[i] = (d < 20) ? g_qT[(bc * DK + d) * HLEN + m0 + m]
                             : g_kT[(bc * DK + d - 20) * HLEN + m0 + m];
        }
        __syncthreads();

        const float isd = 0.22360679774997896f;   // 1/sqrt(20)
        float e[8];
        float esum = 0.f;
        int m = 0, ng = 0;

        // ---- scores + exp (e kept in registers) ----
        if (t < 250) {
            m  = t / 25;
            ng = t - 25 * m;
            float xr[40];
            #pragma unroll
            for (int d = 0; d < 40; d++) xr[d] = xs[d * 10 + m];
            #pragma unroll
            for (int j = 0; j < 8; j++) {
                const int n = ng + 25 * j;
                float s = 0.f;
                #pragma unroll
                for (int d = 0; d < 40; d++)
                    s += xr[d] * ys[d * HLEN + n];
                e[j] = __expf(s * isd);
                esum += e[j];
            }
        }
        __syncthreads();    // ys/xs dead from here

        // ---- phase 2 stage: vt overlays ys region; publish esum ----
        for (int i = t; i < 4000; i += 256) {
            const int d = i / 200, n = i - 200 * d;
            vt[i] = g_vT[(bc * DK + d) * HLEN + n];
        }
        partials[t] = (t < 250) ? esum : 0.f;
        __syncthreads();

        // ---- context partials (unnormalized) + row denominators ----
        if (t < 250) {
            #pragma unroll
            for (int d = 0; d < 20; d++) {
                float c = 0.f;
                #pragma unroll
                for (int j = 0; j < 8; j++)
                    c += e[j] * vt[d * HLEN + ng + 25 * j];
                ctxp[t * 21 + d] = c;
            }
        }
        if (t < 10) {
            float s = 1e-8f;
            #pragma unroll
            for (int q = 0; q < 25; q++)
                s += partials[t * 25 + q];
            rss[t] = 1.f / s;
        }
        __syncthreads();

        // ---- normalized attn writes straight from registers ----
        if (t < 250) {
            const float rs = rss[m];
            float* attn = out + ATTN_OFF + (size_t)(bc * HLEN + m0 + m) * HLEN;
            #pragma unroll
            for (int j = 0; j < 8; j++)
                attn[ng + 25 * j] = e[j] * rs;
        }

        // ---- context reduce + write (200 outputs, 25 partials each) ----
        if (t < 200) {
            const int mm = t / DK, d = t - DK * mm;
            float s = 0.f;
            #pragma unroll
            for (int q = 0; q < 25; q++)
                s += ctxp[(mm * 25 + q) * 21 + d];
            out[(bc * HLEN + m0 + mm) * DK + d] = s * rss[mm];
        }

        // ---- reset counters for the next graph replay ----
        __syncthreads();
        if (t == 0) {
            const int v = atomicAdd(&g_done[bc], 1);
            if (v == ATTN_PER_BC - 1) {
                g_cnt[bc]  = 0;
                g_done[bc] = 0;
                __threadfence();
            }
        }
    }
}

extern "C" void kernel_launch(void* const* d_in, const int* in_sizes, int n_in,
                              void* d_out, int out_size)
{
    const float* Q   = (const float*)d_in[0];
    const float* K   = (const float*)d_in[1];
    const float* V   = (const float*)d_in[2];
    const float* cdd = (const float*)d_in[3];
    const float* W   = (const float*)d_in[4];
    const float* b   = (const float*)d_in[5];
    const float* W1  = (const float*)d_in[6];
    const float* b1  = (const float*)d_in[7];

    mega_kernel<<<TOTAL_BLOCKS, 256, SMEM_BYTES>>>(
        Q, K, V, cdd, W, b, W1, b1, (float*)d_out);
}